// round 3
// baseline (speedup 1.0000x reference)
#include <cuda_runtime.h>
#include <cstdint>

#define BB 2
#define SQ 1024
#define SK 1024
#define DD 64
#define DV 64
#define NSPLIT 32
#define KCHUNK (SK / NSPLIT)   // 32
#define SPB 2                  // splits per block
#define NSG (NSPLIT / SPB)     // 16 stored split-groups
#define QPB 64                 // queries per block
#define TPB 128                // 64 queries x 2 splits

#define LOG2E 1.4426950408889634f
#define ABS2_MASK 0x7FFFFFFF7FFFFFFFULL

typedef unsigned long long ull;

// stored partials after in-block pair reduction: [b][sg(16)][dpair(32)][q(1024)]
__device__ ull   g_pacc[(size_t)BB * NSG * (DV / 2) * SQ];
__device__ float g_pl[(size_t)BB * NSG * SQ];
__device__ int   g_cnt[BB * (SQ / QPB)];   // zero-init; self-resetting tickets

__device__ __forceinline__ ull add_f32x2(ull a, ull b) {
    ull r;
    asm("add.rn.f32x2 %0, %1, %2;" : "=l"(r) : "l"(a), "l"(b));
    return r;
}
__device__ __forceinline__ ull fma_f32x2(ull a, ull b, ull c) {
    ull r;
    asm("fma.rn.f32x2 %0, %1, %2, %3;" : "=l"(r) : "l"(a), "l"(b), "l"(c));
    return r;
}
__device__ __forceinline__ ull pack_dup(float p) {
    ull r;
    asm("mov.b64 %0, {%1, %1};" : "=l"(r) : "r"(__float_as_uint(p)));
    return r;
}
__device__ __forceinline__ float ex2(float x) {
    float r;
    asm("ex2.approx.f32 %0, %1;" : "=f"(r) : "f"(x));
    return r;
}

// L1 distance over 64 dims: 16 LDS.128, 32 packed diffs, 32 LOP3 abs,
// 31 packed adds via 8 low-pressure accumulator chains, 1 scalar add.
__device__ __forceinline__ float l1_64(const ulonglong2* __restrict__ kp,
                                       const ull* __restrict__ qn)
{
    ull s[8];
#pragma unroll
    for (int i = 0; i < 4; i++) {
        ulonglong2 kk = kp[i];
        s[2 * i]     = add_f32x2(kk.x, qn[2 * i])     & ABS2_MASK;
        s[2 * i + 1] = add_f32x2(kk.y, qn[2 * i + 1]) & ABS2_MASK;
    }
#pragma unroll
    for (int i = 4; i < 16; i++) {
        ulonglong2 kk = kp[i];
        s[(2 * i) & 7]     = add_f32x2(s[(2 * i) & 7],
                                       add_f32x2(kk.x, qn[2 * i]) & ABS2_MASK);
        s[(2 * i + 1) & 7] = add_f32x2(s[(2 * i + 1) & 7],
                                       add_f32x2(kk.y, qn[2 * i + 1]) & ABS2_MASK);
    }
    s[0] = add_f32x2(s[0], s[4]);
    s[1] = add_f32x2(s[1], s[5]);
    s[2] = add_f32x2(s[2], s[6]);
    s[3] = add_f32x2(s[3], s[7]);
    s[0] = add_f32x2(s[0], s[2]);
    s[1] = add_f32x2(s[1], s[3]);
    s[0] = add_f32x2(s[0], s[1]);
    float2 f = *(float2*)&s[0];
    return f.x + f.y;
}

__global__ __launch_bounds__(TPB, 3)
void attn_fused(const float* __restrict__ q, const float* __restrict__ k,
                const float* __restrict__ v, const int* __restrict__ mask,
                float* __restrict__ out)
{
    const int b    = blockIdx.z;
    const int sg   = blockIdx.y;          // split group 0..15
    const int qt   = blockIdx.x;          // q tile 0..15
    const int tid  = threadIdx.x;
    const int h    = tid >> 6;            // which split of the pair (0/1)
    const int qloc = tid & 63;
    const int qi   = qt * QPB + qloc;
    const int S    = sg * SPB + h;        // global split 0..31

    __shared__ __align__(16) float ks[SPB][KCHUNK][DD];      // 16KB
    __shared__ __align__(16) float vs[SPB][KCHUNK][DV];      // 16KB
    __shared__ __align__(16) float k0s[DD];
    __shared__ float bias[SPB][KCHUNK];
    __shared__ __align__(16) ull  pbuf[QPB][DV / 2 + 1];     // padded: ~17KB
    __shared__ float lbuf[QPB];
    __shared__ float linv_s[QPB];
    __shared__ int   flag_s;

    // each split-half cooperatively loads its own K/V chunk
    {
        const float* kb = k + ((size_t)b * SK + (size_t)S * KCHUNK) * DD;
        const float* vb = v + ((size_t)b * SK + (size_t)S * KCHUNK) * DV;
#pragma unroll
        for (int i = qloc; i < KCHUNK * DD / 4; i += QPB) {
            ((float4*)&ks[h][0][0])[i] = ((const float4*)kb)[i];
            ((float4*)&vs[h][0][0])[i] = ((const float4*)vb)[i];
        }
        if (qloc < KCHUNK)
            bias[h][qloc] = mask[(size_t)b * SK + (size_t)S * KCHUNK + qloc] ? 0.0f : 1e9f;
        if (tid < DD / 4)
            ((float4*)k0s)[tid] = ((const float4*)(k + (size_t)b * SK * DD))[tid];
    }

    // this thread's negated q row, packed f32x2 (32 ull)
    ull qn[DD / 2];
    {
        const float* qrow = q + ((size_t)b * SQ + qi) * DD;
#pragma unroll
        for (int i = 0; i < DD / 4; i++) {
            float4 t = ((const float4*)qrow)[i];
            float2 a = make_float2(-t.x, -t.y);
            float2 c = make_float2(-t.z, -t.w);
            qn[2 * i]     = *(ull*)&a;
            qn[2 * i + 1] = *(ull*)&c;
        }
    }
    __syncthreads();

    // shared reference point (identical for both halves of a query pair,
    // identical across all splits): dist0 = L1(q, k[b][0])
    float dist0 = l1_64((const ulonglong2*)k0s, qn);
    float d0l2  = dist0 * LOG2E;

    ull acc[DV / 2];
#pragma unroll
    for (int i = 0; i < DV / 2; i++) acc[i] = 0ULL;
    float lsum = 0.0f;

#pragma unroll 2
    for (int j = 0; j < KCHUNK; j++) {
        float bj   = bias[h][j];
        float dist = l1_64((const ulonglong2*)&ks[h][j][0], qn);
        float p    = ex2(fmaf(dist + bj, -LOG2E, d0l2));   // exp(d0 - dist - bias)
        lsum += p;
        ull pp = pack_dup(p);

        const ulonglong2* vp = (const ulonglong2*)&vs[h][j][0];
#pragma unroll
        for (int i = 0; i < DV / 4; i++) {
            ulonglong2 vv = vp[i];
            acc[2 * i]     = fma_f32x2(vv.x, pp, acc[2 * i]);
            acc[2 * i + 1] = fma_f32x2(vv.y, pp, acc[2 * i + 1]);
        }
    }

    // in-block pair reduction: split 1 -> smem, split 0 adds + stores
    if (h == 1) {
#pragma unroll
        for (int i = 0; i < DV / 2; i++) pbuf[qloc][i] = acc[i];
        lbuf[qloc] = lsum;
    }
    __syncthreads();
    if (h == 0) {
        ull* pb = g_pacc + ((size_t)(b * NSG + sg) * (DV / 2)) * SQ;
#pragma unroll
        for (int i = 0; i < DV / 2; i++) {
            ull m = add_f32x2(acc[i], pbuf[qloc][i]);
            pb[(size_t)i * SQ + qi] = m;
        }
        g_pl[(size_t)(b * NSG + sg) * SQ + qi] = lsum + lbuf[qloc];
    }

    // ticket: the 16th block for this (b, qtile) performs the combine
    __threadfence();
    __syncthreads();
    if (tid == 0) {
        int c = atomicAdd(&g_cnt[b * (SQ / QPB) + qt], 1);
        flag_s = (c == NSG - 1);
        if (c == NSG - 1) g_cnt[b * (SQ / QPB) + qt] = 0;   // reset for next replay
    }
    __syncthreads();
    if (!flag_s) return;
    __threadfence();

    // ---- combine for this (b, qtile): thread = (query qloc, d-half h) ----
    if (h == 0) {
        float lt = 0.0f;
#pragma unroll
        for (int s2 = 0; s2 < NSG; s2++)
            lt += g_pl[(size_t)(b * NSG + s2) * SQ + qi];
        linv_s[qloc] = 1.0f / lt;
    }

    float sx[16], sy[16];
#pragma unroll
    for (int d2 = 0; d2 < 16; d2++) { sx[d2] = 0.0f; sy[d2] = 0.0f; }
#pragma unroll
    for (int s2 = 0; s2 < NSG; s2++) {
        const ull* base = g_pacc +
            ((size_t)(b * NSG + s2) * (DV / 2) + h * 16) * SQ + qi;
#pragma unroll
        for (int d2 = 0; d2 < 16; d2++) {
            ull t = base[(size_t)d2 * SQ];
            float2 f = *(float2*)&t;
            sx[d2] += f.x;
            sy[d2] += f.y;
        }
    }
    __syncthreads();
    float li = linv_s[qloc];
    float* orow = out + ((size_t)b * SQ + qi) * DV + h * 32;
#pragma unroll
    for (int d2 = 0; d2 < 16; d2++) {
        float2 r = make_float2(sx[d2] * li, sy[d2] * li);
        *(float2*)(orow + 2 * d2) = r;
    }
}

extern "C" void kernel_launch(void* const* d_in, const int* in_sizes, int n_in,
                              void* d_out, int out_size)
{
    const float* q    = (const float*)d_in[0];
    const float* k    = (const float*)d_in[1];
    const float* v    = (const float*)d_in[2];
    const int*   mask = (const int*)d_in[3];
    float* out = (float*)d_out;

    dim3 grid(SQ / QPB, NSG, BB);
    attn_fused<<<grid, TPB>>>(q, k, v, mask, out);
}

// round 4
// speedup vs baseline: 1.2066x; 1.2066x over previous
#include <cuda_runtime.h>
#include <cstdint>

#define BB 2
#define SQ 1024
#define SK 1024
#define DD 64
#define DV 64
#define NSPLIT 32
#define KCHUNK 32              // SK / NSPLIT
#define KB 16                  // k sub-block staged through hbuf
#define QPB 64
#define TPB 128
#define NTILE 16               // SQ / QPB
#define NTAIL 4                // tail blocks participating in combine

#define LOG2E 1.4426950408889634f
#define ABS2_MASK 0x7FFFFFFF7FFFFFFFULL

typedef unsigned long long ull;

// partials: [b][split][dpair(32)][q(1024)]  (16MB, L2-resident)
__device__ ull   g_pacc[(size_t)BB * NSPLIT * (DV / 2) * SQ];
__device__ float g_pl[(size_t)BB * NSPLIT * SQ];
__device__ int   g_cnt[BB * NTILE];   // arrival tickets (self-resetting)
__device__ int   g_fin[BB * NTILE];   // combine completions (self-resetting)

__device__ __forceinline__ ull add_f32x2(ull a, ull b) {
    ull r;
    asm("add.rn.f32x2 %0, %1, %2;" : "=l"(r) : "l"(a), "l"(b));
    return r;
}
__device__ __forceinline__ ull fma_f32x2(ull a, ull b, ull c) {
    ull r;
    asm("fma.rn.f32x2 %0, %1, %2, %3;" : "=l"(r) : "l"(a), "l"(b), "l"(c));
    return r;
}
__device__ __forceinline__ ull pack_dup(float p) {
    ull r;
    asm("mov.b64 %0, {%1, %1};" : "=l"(r) : "r"(__float_as_uint(p)));
    return r;
}
__device__ __forceinline__ float ex2(float x) {
    float r;
    asm("ex2.approx.f32 %0, %1;" : "=f"(r) : "f"(x));
    return r;
}

// L1 distance over 32 dims: 8 LDS.128, 16 packed diffs + abs, 4 accumulation
// chains (low register pressure), final scalar add.
__device__ __forceinline__ float l1_32(const ulonglong2* __restrict__ kp,
                                       const ull* __restrict__ qn)
{
    ulonglong2 k0 = kp[0];
    ulonglong2 k1 = kp[1];
    ull s0 = add_f32x2(k0.x, qn[0]) & ABS2_MASK;
    ull s1 = add_f32x2(k0.y, qn[1]) & ABS2_MASK;
    ull s2 = add_f32x2(k1.x, qn[2]) & ABS2_MASK;
    ull s3 = add_f32x2(k1.y, qn[3]) & ABS2_MASK;
#pragma unroll
    for (int i = 2; i < 8; i += 2) {
        ulonglong2 ka = kp[i];
        ulonglong2 kb = kp[i + 1];
        s0 = add_f32x2(s0, add_f32x2(ka.x, qn[2 * i])     & ABS2_MASK);
        s1 = add_f32x2(s1, add_f32x2(ka.y, qn[2 * i + 1]) & ABS2_MASK);
        s2 = add_f32x2(s2, add_f32x2(kb.x, qn[2 * i + 2]) & ABS2_MASK);
        s3 = add_f32x2(s3, add_f32x2(kb.y, qn[2 * i + 3]) & ABS2_MASK);
    }
    s0 = add_f32x2(s0, s2);
    s1 = add_f32x2(s1, s3);
    s0 = add_f32x2(s0, s1);
    float2 f = *(float2*)&s0;
    return f.x + f.y;
}

__global__ __launch_bounds__(TPB, 5)
void attn_fused(const float* __restrict__ q, const float* __restrict__ k,
                const float* __restrict__ v, const int* __restrict__ mask,
                float* __restrict__ out)
{
    const int b    = blockIdx.z;
    const int sg   = blockIdx.y;          // split 0..31
    const int qt   = blockIdx.x;          // q tile 0..15
    const int tid  = threadIdx.x;
    const int h    = tid >> 6;            // dim half (and j-half in phase 1b)
    const int qloc = tid & 63;
    const int qi   = qt * QPB + qloc;

    __shared__ __align__(16) float ks[KCHUNK][DD];        // 8KB
    __shared__ __align__(16) float vs[KCHUNK][DV];        // 8KB
    __shared__ __align__(16) float hbuf[KB][2][QPB];      // 8KB half-dists / p
    __shared__ __align__(16) float k0s[DD];
    __shared__ float bias[KCHUNK];
    __shared__ float d0b[2][QPB];
    __shared__ float lb[2][QPB];
    __shared__ int   rank_s;

    // cooperative loads: K/V chunk, mask bias, reference row k0
    {
        const float* kb = k + ((size_t)b * SK + (size_t)sg * KCHUNK) * DD;
        const float* vb = v + ((size_t)b * SK + (size_t)sg * KCHUNK) * DV;
#pragma unroll
        for (int i = tid; i < KCHUNK * DD / 4; i += TPB) {
            ((float4*)&ks[0][0])[i] = ((const float4*)kb)[i];
            ((float4*)&vs[0][0])[i] = ((const float4*)vb)[i];
        }
        if (tid < KCHUNK)
            bias[tid] = mask[(size_t)b * SK + (size_t)sg * KCHUNK + tid] ? 0.0f : 1e9f;
        if (tid < DD / 4)
            ((float4*)k0s)[tid] = ((const float4*)(k + (size_t)b * SK * DD))[tid];
    }

    // this thread's negated q half (dims [32h, 32h+32)), packed f32x2: 16 ull
    ull qn[16];
    {
        const float* qrow = q + ((size_t)b * SQ + qi) * DD + 32 * h;
#pragma unroll
        for (int i = 0; i < 8; i++) {
            float4 t = ((const float4*)qrow)[i];
            float2 a = make_float2(-t.x, -t.y);
            float2 c = make_float2(-t.z, -t.w);
            qn[2 * i]     = *(ull*)&a;
            qn[2 * i + 1] = *(ull*)&c;
        }
    }
    __syncthreads();

    // shared reference point: dist0 = L1(q, k[b][0]), halves joined via smem
    d0b[h][qloc] = l1_32((const ulonglong2*)(k0s + 32 * h), qn);
    __syncthreads();
    const float d0l2 = (d0b[0][qloc] + d0b[1][qloc]) * LOG2E;

    ull acc[16];                       // this thread's 32 output dims
#pragma unroll
    for (int i = 0; i < 16; i++) acc[i] = 0ULL;
    float lsum = 0.0f;

#pragma unroll 1
    for (int jb = 0; jb < KCHUNK; jb += KB) {
        // phase 1a: half-distances for KB keys (independent iterations)
#pragma unroll
        for (int j = 0; j < KB; j++)
            hbuf[j][h][qloc] = l1_32((const ulonglong2*)&ks[jb + j][32 * h], qn);
        __syncthreads();

        // phase 1b: join halves, softmax numerator p, write back in place
#pragma unroll
        for (int t = 0; t < KB / 2; t++) {
            int j = h * (KB / 2) + t;
            float d = hbuf[j][0][qloc] + hbuf[j][1][qloc];
            float p = ex2(fmaf(d + bias[jb + j], -LOG2E, d0l2));
            hbuf[j][0][qloc] = p;
            lsum += p;
        }
        __syncthreads();

        // phase 2: AV accumulation over this sub-block (independent chains)
#pragma unroll
        for (int j = 0; j < KB; j++) {
            ull pp = pack_dup(hbuf[j][0][qloc]);
            const ulonglong2* vp = (const ulonglong2*)&vs[jb + j][32 * h];
#pragma unroll
            for (int i = 0; i < 8; i++) {
                ulonglong2 vv = vp[i];
                acc[2 * i]     = fma_f32x2(vv.x, pp, acc[2 * i]);
                acc[2 * i + 1] = fma_f32x2(vv.y, pp, acc[2 * i + 1]);
            }
        }
        __syncthreads();   // protect hbuf before next sub-block overwrites
    }

    // store partials (coalesced STG.64) + denominators
    {
        ull* pb = g_pacc + ((size_t)(b * NSPLIT + sg) * (DV / 2)) * SQ;
#pragma unroll
        for (int i = 0; i < 16; i++)
            pb[(size_t)(h * 16 + i) * SQ + qi] = acc[i];
        lb[h][qloc] = lsum;
    }
    __syncthreads();
    if (h == 0)
        g_pl[(size_t)(b * NSPLIT + sg) * SQ + qi] = lsum + lb[1][qloc];

    // ---- arrival ticket: last NTAIL blocks per (b, qtile) combine ----
    const int tile = b * NTILE + qt;
    __threadfence();
    __syncthreads();
    if (tid == 0) rank_s = atomicAdd(&g_cnt[tile], 1);
    __syncthreads();
    const int c = rank_s;
    if (c < NSPLIT - NTAIL) return;

    if (tid == 0) {
        while (*(volatile int*)&g_cnt[tile] < NSPLIT) { }
    }
    __syncthreads();
    __threadfence();

    const int r = c - (NSPLIT - NTAIL);      // 0..3 -> dp slice [8r, 8r+8)

    // denominator for this thread's query (fixed order -> deterministic)
    float lt = 0.0f;
#pragma unroll
    for (int s2 = 0; s2 < NSPLIT; s2++)
        lt += g_pl[(size_t)(b * NSPLIT + s2) * SQ + qi];
    const float li = 1.0f / lt;

    const int dpb = r * 8 + h * 4;
    ull a[4] = {0ULL, 0ULL, 0ULL, 0ULL};
#pragma unroll
    for (int s2 = 0; s2 < NSPLIT; s2++) {
        const ull* base = g_pacc + ((size_t)(b * NSPLIT + s2) * (DV / 2)) * SQ + qi;
#pragma unroll
        for (int i = 0; i < 4; i++)
            a[i] = add_f32x2(a[i], base[(size_t)(dpb + i) * SQ]);
    }
#pragma unroll
    for (int i = 0; i < 4; i++) {
        float2 f = *(float2*)&a[i];
        float2 rr = make_float2(f.x * li, f.y * li);
        *(float2*)&out[((size_t)b * SQ + qi) * DV + 2 * (dpb + i)] = rr;
    }

    // completion counter: 4th finisher resets both tickets for graph replay
    __threadfence();
    __syncthreads();
    if (tid == 0) {
        int f = atomicAdd(&g_fin[tile], 1);
        if (f == NTAIL - 1) {
            g_cnt[tile] = 0;
            g_fin[tile] = 0;
            __threadfence();
        }
    }
}

extern "C" void kernel_launch(void* const* d_in, const int* in_sizes, int n_in,
                              void* d_out, int out_size)
{
    const float* q    = (const float*)d_in[0];
    const float* k    = (const float*)d_in[1];
    const float* v    = (const float*)d_in[2];
    const int*   mask = (const int*)d_in[3];
    float* out = (float*)d_out;

    dim3 grid(NTILE, NSPLIT, BB);
    attn_fused<<<grid, TPB>>>(q, k, v, mask, out);
}